// round 6
// baseline (speedup 1.0000x reference)
#include <cuda_runtime.h>
#include <cuda_fp16.h>

// ForwardWarp: forward splatting with Gaussian softmax weights.
// img, counts: (8,1,720,1280) f32; flo: (8,2,720,1280) f32 (ch0 = y shifts W axis, ch1 = x shifts H axis)
// out: [0:S) = img_warp / (one_warp + eps), [S:2S) = one_warp
//
// Splat is LTS atomic-quantum bound (~2.9e11 8B-quanta/s). f16x2 payload {img*cw, cw}
// gives 2 quanta/pixel (one red.global.add.noftz.v2.f16x2 per tap-row). R5 showed fp16
// ACCUMULATION rounding (not packing) breaks 1e-3. Fix: 4 accumulator copies, hashed so
// each (cell,copy) gets ~1 add -> only packing error remains. Copies A0/A1 = natural
// layout (even column pairs), B0/B1 = shifted one cell (odd pairs 8B-aligned).
// 2 batch-chunks keep the live scratch (59MB) L2-resident. Normalize sums 4 halves in
// fp32, writes outputs, and restores zeros (exact slots it read -> race-free, no memset).

static constexpr int N_ = 8;
static constexpr int H_ = 720;
static constexpr int W_ = 1280;
static constexpr int S_ = N_ * H_ * W_;    // 7,372,800
static constexpr int HALF_ = S_ / 2;       // 4 images per chunk
static constexpr float EPS_ = 1e-6f;

// cell = f16x2 {img_weighted, one_weighted} (4B).
// A copies: cell q at g_A*[q]     (v2 target 8B-aligned when q even)
// B copies: cell q at g_B*[q+1]   (v2 target 8B-aligned when q odd)
__device__ __align__(16) unsigned int g_A0[S_];
__device__ __align__(16) unsigned int g_A1[S_];
__device__ __align__(16) unsigned int g_B0[S_ + 8];
__device__ __align__(16) unsigned int g_B1[S_ + 8];

__device__ __forceinline__ void red_h2v2(unsigned int* p, unsigned int r0, unsigned int r1) {
    asm volatile("red.global.add.noftz.v2.f16x2 [%0], {%1, %2};"
                 :: "l"(p), "r"(r0), "r"(r1) : "memory");
}
__device__ __forceinline__ void red_h2(unsigned int* p, unsigned int r) {
    asm volatile("red.global.add.noftz.f16x2 [%0], %1;"
                 :: "l"(p), "r"(r) : "memory");
}
__device__ __forceinline__ unsigned int pack_h2(float a, float b) {
    __half2 h = __float22half2_rn(make_float2(a, b));
    return *reinterpret_cast<unsigned int*>(&h);
}
__device__ __forceinline__ float2 unpack_h2(unsigned int u) {
    return __half22float2(*reinterpret_cast<__half2*>(&u));
}

__global__ void __launch_bounds__(256) splat_kernel(
    const float* __restrict__ img,
    const float* __restrict__ counts,
    const float* __restrict__ flo,
    int chunk)
{
    int idx = chunk * HALF_ + blockIdx.x * blockDim.x + threadIdx.x;

    int w  = idx % W_;
    int hw = idx / W_;
    int h  = hw % H_;
    int n  = hw / H_;

    // flo layout: (N, 2, H, W). channel 0 = y (shifts W axis), channel 1 = x (shifts H axis)
    int flo_base = ((n * 2) * H_ + h) * W_ + w;
    float y = flo[flo_base];
    float x = flo[flo_base + H_ * W_];

    float im = img[idx];
    float c  = counts[idx];

    float x1 = floorf(x);
    float y1 = floorf(y);
    float fx = x - x1;            // (x - x1) in [0,1)
    float fy = y - y1;
    float gx = fx - 1.0f;         // (x - x2)
    float gy = fy - 1.0f;

    float dx1 = fx * fx, dx2 = gx * gx;
    float dy1 = fy * fy, dy2 = gy * gy;

    float w11 = __expf(-(dx1 + dy1));
    float w12 = __expf(-(dx1 + dy2));
    float w21 = __expf(-(dx2 + dy1));
    float w22 = __expf(-(dx2 + dy2));
    float inv = 1.0f / (w11 + w12 + w21 + w22);

    float cinv = c * inv;
    float wa1 = w11 * cinv, wb1 = w12 * cinv;   // row ix1: columns iy1, iy2
    float wa2 = w21 * cinv, wb2 = w22 * cinv;   // row ix2

    int ix1 = (int)x1 + h;
    int ix2 = ix1 + 1;
    int iy1 = (int)y1 + w;
    int iy2 = iy1 + 1;

    bool va = (iy1 >= 0) & (iy1 < W_);
    bool vb = (iy2 >= 0) & (iy2 < W_);
    if (!(va | vb)) return;

    int nb = n * H_;
    bool odd = (iy1 & 1);
    int sel = ((w >> 1) + h) & 1;               // copy hash (decorrelates colliders)

    unsigned int* baseA = sel ? g_A1 : g_A0;
    unsigned int* baseB = sel ? g_B1 : g_B0;

    // row 1
    if (ix1 >= 0 && ix1 < H_) {
        int q = (nb + ix1) * W_ + iy1;
        if (va & vb) {
            unsigned int r0 = pack_h2(im * wa1, wa1);
            unsigned int r1 = pack_h2(im * wb1, wb1);
            if (odd) red_h2v2(baseB + q + 1, r0, r1);
            else     red_h2v2(baseA + q,     r0, r1);
        } else if (va) {
            red_h2(baseA + q,     pack_h2(im * wa1, wa1));
        } else {
            red_h2(baseA + q + 1, pack_h2(im * wb1, wb1));
        }
    }
    // row 2
    if (ix2 >= 0 && ix2 < H_) {
        int q = (nb + ix2) * W_ + iy1;
        if (va & vb) {
            unsigned int r0 = pack_h2(im * wa2, wa2);
            unsigned int r1 = pack_h2(im * wb2, wb2);
            if (odd) red_h2v2(baseB + q + 1, r0, r1);
            else     red_h2v2(baseA + q,     r0, r1);
        } else if (va) {
            red_h2(baseA + q,     pack_h2(im * wa2, wa2));
        } else {
            red_h2(baseA + q + 1, pack_h2(im * wb2, wb2));
        }
    }
}

// Strided per-thread cells: every access coalesced. Each thread reads A[c], B[c+1]
// (its exclusive slots), sums 4 halves in fp32, writes both outputs, zero-restores
// exactly the slots it read (disjoint across threads -> race-free).
static constexpr int NORM_THREADS_ = 256;
static constexpr int NORM_CELLS_PER_ = 8;

__global__ void __launch_bounds__(256) normalize_kernel(float* __restrict__ out, int chunk)
{
    int base = chunk * HALF_ + blockIdx.x * (NORM_THREADS_ * NORM_CELLS_PER_) + threadIdx.x;

    #pragma unroll
    for (int k = 0; k < NORM_CELLS_PER_; k++) {
        int c = base + k * NORM_THREADS_;
        unsigned int a0 = g_A0[c];
        unsigned int a1 = g_A1[c];
        unsigned int b0 = g_B0[c + 1];
        unsigned int b1 = g_B1[c + 1];

        float2 f0 = unpack_h2(a0);
        float2 f1 = unpack_h2(a1);
        float2 f2 = unpack_h2(b0);
        float2 f3 = unpack_h2(b1);

        float one = (f0.y + f1.y) + (f2.y + f3.y);
        float num = (f0.x + f1.x) + (f2.x + f3.x);
        out[c]      = num / (one + EPS_);
        out[S_ + c] = one;

        g_A0[c] = 0u;
        g_A1[c] = 0u;
        g_B0[c + 1] = 0u;
        g_B1[c + 1] = 0u;
    }
}

extern "C" void kernel_launch(void* const* d_in, const int* in_sizes, int n_in,
                              void* d_out, int out_size)
{
    const float* img    = (const float*)d_in[0];
    const float* counts = (const float*)d_in[1];
    const float* flo    = (const float*)d_in[2];
    float* out = (float*)d_out;

    int splat_blocks = HALF_ / 256;                                   // 14400
    int norm_blocks  = HALF_ / (NORM_THREADS_ * NORM_CELLS_PER_);     // 1800

    for (int chunk = 0; chunk < 2; chunk++) {
        splat_kernel<<<splat_blocks, 256>>>(img, counts, flo, chunk);
        normalize_kernel<<<norm_blocks, NORM_THREADS_>>>(out, chunk);
    }
}